// round 14
// baseline (speedup 1.0000x reference)
#include <cuda_runtime.h>
#include <cuda_bf16.h>
#include <math.h>
#include <stdint.h>

#define Gn   256      // graphs
#define Nn   512      // nodes per graph
#define En   16384    // edges per graph
#define Hh   256      // hidden
#define FIN  4
#define TASKS 512     // 256 home + 256 away
#define HP   128      // Hh/2 pairs

// ---------------- scratch (device globals; no allocation) ----------------
__device__ __align__(16) uint32_t      g_C [(size_t)TASKS * Nn * HP];  // T ping
__device__ __align__(16) uint32_t      g_C2[(size_t)TASKS * Nn * HP];  // T pong
__device__ __align__(16) __nv_bfloat16 g_Ad[(size_t)TASKS * Nn * Nn]; // dense normalized adjacency
__device__ float g_dinv[TASKS * Nn];
__device__ float g_selfnorm[TASKS * Nn];
__device__ float g_pool[TASKS * Hh];
__device__ __nv_bfloat16 g_Wtb[4 * Hh * Hh];                // bf16 weights, [l][n][k]

__device__ __forceinline__ uint32_t smem_u32(const void* p) {
    uint32_t a;
    asm("{ .reg .u64 t; cvta.to.shared.u64 t, %1; cvt.u32.u64 %0, t; }" : "=r"(a) : "l"(p));
    return a;
}
__device__ __forceinline__ void cpasync16(uint32_t dst, const void* src) {
    asm volatile("cp.async.cg.shared.global [%0], [%1], 16;" :: "r"(dst), "l"(src) : "memory");
}
__device__ __forceinline__ void ldsm_x4(uint32_t& r0, uint32_t& r1, uint32_t& r2, uint32_t& r3,
                                        uint32_t addr) {
    asm volatile("ldmatrix.sync.aligned.m8n8.x4.shared.b16 {%0,%1,%2,%3}, [%4];"
                 : "=r"(r0), "=r"(r1), "=r"(r2), "=r"(r3) : "r"(addr));
}
__device__ __forceinline__ void ldsm_x4_t(uint32_t& r0, uint32_t& r1, uint32_t& r2, uint32_t& r3,
                                          uint32_t addr) {
    asm volatile("ldmatrix.sync.aligned.m8n8.x4.trans.shared.b16 {%0,%1,%2,%3}, [%4];"
                 : "=r"(r0), "=r"(r1), "=r"(r2), "=r"(r3) : "r"(addr));
}
__device__ __forceinline__ void mma_bf16(float* c, const uint32_t* a, const uint32_t* b) {
    asm volatile(
        "mma.sync.aligned.m16n8k16.row.col.f32.bf16.bf16.f32 "
        "{%0,%1,%2,%3}, {%4,%5,%6,%7}, {%8,%9}, {%0,%1,%2,%3};"
        : "+f"(c[0]), "+f"(c[1]), "+f"(c[2]), "+f"(c[3])
        : "r"(a[0]), "r"(a[1]), "r"(a[2]), "r"(a[3]), "r"(b[0]), "r"(b[1]));
}

// ---------------- prep: degree -> dinv/selfnorm (smem histogram) ----------------
__global__ void prep_init() {                  // zero pool
    g_pool[blockIdx.x * 256 + threadIdx.x] = 0.0f;
}

__global__ __launch_bounds__(512) void prep_degree(
        const int* __restrict__ hei, const int* __restrict__ aei,
        const float* __restrict__ hew, const float* __restrict__ aew) {
    __shared__ float sdeg[Nn];
    int task = blockIdx.x, tid = threadIdx.x;
    sdeg[tid] = 1.0f;      // self-loop weight
    __syncthreads();
    const int*   ei = (task < Gn) ? hei + (size_t)task * 2 * En : aei + (size_t)(task - Gn) * 2 * En;
    const float* ew = (task < Gn) ? hew + (size_t)task * En     : aew + (size_t)(task - Gn) * En;
#pragma unroll 4
    for (int it = 0; it < En / 512; it++) {
        int e = it * 512 + tid;
        atomicAdd(&sdeg[ei[En + e]], ew[e]);
    }
    __syncthreads();
    float di = rsqrtf(sdeg[tid]);
    g_dinv[task * Nn + tid] = di;
    g_selfnorm[task * Nn + tid] = di * di;
}

// ---------------- fused dense adjacency build: zero + scatter, L2-resident (r12 WIN) ----------------
#define BAD_CTAS 128

__global__ __launch_bounds__(512) void build_Ad3(
        const int* __restrict__ hei, const int* __restrict__ aei,
        const float* __restrict__ hew, const float* __restrict__ aew) {
    __shared__ float sdinv[Nn];
    const int tid = threadIdx.x;

    for (int task = blockIdx.x; task < TASKS; task += BAD_CTAS) {
        __nv_bfloat16* Ad = g_Ad + (size_t)task * Nn * Nn;

        for (int i = tid; i < Nn * Nn / 8; i += 512)
            ((uint4*)Ad)[i] = make_uint4(0, 0, 0, 0);
        sdinv[tid] = g_dinv[task * Nn + tid];
        __syncthreads();

        const int*   ei = (task < Gn) ? hei + (size_t)task * 2 * En
                                      : aei + (size_t)(task - Gn) * 2 * En;
        const float* ew = (task < Gn) ? hew + (size_t)task * En
                                      : aew + (size_t)(task - Gn) * En;
#pragma unroll 4
        for (int it = 0; it < En / 512; it++) {
            int e = it * 512 + tid;
            int s = ei[e];
            int t = ei[En + e];
            float norm = sdinv[s] * ew[e] * sdinv[t];
            atomicAdd(Ad + (size_t)t * Nn + s, __float2bfloat16(norm));
        }
        atomicAdd(Ad + (size_t)tid * Nn + tid, __float2bfloat16(g_selfnorm[task * Nn + tid]));
        __syncthreads();
    }
}

// ---------------- weight prep: Wtb[l][n][k] = bf16(Wh[l][k][n]) ----------------
__global__ void wt_prep(const float* __restrict__ Wh) {
    int l = blockIdx.y, n = blockIdx.x, k = threadIdx.x;
    g_Wtb[(size_t)l * Hh * Hh + (size_t)n * Hh + k] =
        __float2bfloat16(Wh[(size_t)l * Hh * Hh + (size_t)k * Hh + n]);
}

// ---------------- layer 0 GEMM: C = X[512,4] @ W0[4,256], bf16-pair out ----------------
__global__ void gemm0(const float* __restrict__ hx, const float* __restrict__ ax,
                      const float* __restrict__ W0) {
    int task = blockIdx.x;
    int n0 = blockIdx.y * 8;
    int h = threadIdx.x;     // pair index 0..127
    const float* x = (task < Gn) ? hx + (size_t)task * Nn * FIN
                                 : ax + (size_t)(task - Gn) * Nn * FIN;
    float wa0 = W0[2 * h],            wb0 = W0[2 * h + 1];
    float wa1 = W0[Hh + 2 * h],       wb1 = W0[Hh + 2 * h + 1];
    float wa2 = W0[2 * Hh + 2 * h],   wb2 = W0[2 * Hh + 2 * h + 1];
    float wa3 = W0[3 * Hh + 2 * h],   wb3 = W0[3 * Hh + 2 * h + 1];
    uint32_t* C = g_C + (size_t)task * Nn * HP;
#pragma unroll
    for (int i = 0; i < 8; i++) {
        int n = n0 + i;
        float4 xv = *(const float4*)(x + n * 4);
        float c0 = xv.x * wa0 + xv.y * wa1 + xv.z * wa2 + xv.w * wa3;
        float c1 = xv.x * wb0 + xv.y * wb1 + xv.z * wb2 + xv.w * wb3;
        __nv_bfloat162 p = __float22bfloat162_rn(make_float2(c0, c1));
        C[n * HP + h] = *reinterpret_cast<uint32_t*>(&p);
    }
}

// ---------------- fused GCN layer: H = relu(Ahat @ T + b); T' = H @ W ----------------
// CTA: 64 rows x 256 channels; grid (8 m-blocks, TASKS), 128 threads = 4 warps (1m x 4n).
// Phase 1: Ahat[64,512] @ T[512,256] via k=32 chunks (Ahat 80B rows; T 512B rows XOR-swizzled, trans-ldsm)
// Phase 2: H[64,256](smem, 528B stride) @ W[256,256] via k=16 chunks (W 48B rows), same acc regs.
#define AST  40
#define ACHB (64 * AST * 2)      // 5120  Ahat chunk
#define TCHB 16384               //       T chunk [32k][256n]
#define HST  528                 // H row stride bytes (33x16, odd units -> conflict-free)
#define HSZ  (64 * HST)          // 33792
#define WST  48                  // W chunk row stride (3x16)
#define WCH2 (256 * WST)         // 12288 W chunk [256n][16k]
#define FUS_SMEM (2 * ACHB + 2 * TCHB + HSZ + 2 * WCH2)   // 101376

__global__ __launch_bounds__(128) void layer_fused(int bufsel, int layer,
                                                   const float* __restrict__ bias, int do_pool) {
    extern __shared__ __align__(128) char smg[];
    const uint32_t sm0 = smem_u32(smg);
    const uint32_t smA = sm0;                       // 2 x ACHB
    const uint32_t smT = sm0 + 2 * ACHB;            // 2 x TCHB
    const uint32_t smH = smT + 2 * TCHB;            // HSZ
    const uint32_t smW = smH + HSZ;                 // 2 x WCH2

    const int task = blockIdx.y;
    const int bm = blockIdx.x * 64;
    const uint32_t* Tin  = bufsel ? g_C2 : g_C;
    uint32_t*       Tout = bufsel ? g_C  : g_C2;
    const __nv_bfloat16* A = g_Ad + (size_t)task * Nn * Nn + (size_t)bm * Nn;
    const __nv_bfloat16* T = (const __nv_bfloat16*)(Tin + (size_t)task * Nn * HP);
    uint32_t* Co = Tout + (size_t)task * Nn * HP + (size_t)bm * HP;

    const int tid  = threadIdx.x;
    const int lane = tid & 31;
    const int wid  = tid >> 5;
    const int n_off = wid * 64;
    const int gid = lane >> 2;
    const int tig = lane & 3;

    const int a_row = (lane & 15);
    const int a_kc  = (lane >> 4) * 8;
    const int b_row = (lane & 7) + (lane >> 4) * 8;
    const int b_kc  = ((lane >> 3) & 1) * 8;
    const int bt_kr = (lane & 15);
    const int bt_nc = (lane >> 4) * 8;

    float acc[4][8][4];
#pragma unroll
    for (int mi = 0; mi < 4; mi++)
#pragma unroll
        for (int ni = 0; ni < 8; ni++)
#pragma unroll
            for (int q = 0; q < 4; q++) acc[mi][ni][q] = 0.f;

    // ---------- phase 1: Ahat @ T ----------
#define AISSUE(kb)                                                              \
    {                                                                           \
        int _buf = (kb) & 1;                                                    \
        uint32_t _da = smA + _buf * ACHB;                                       \
        uint32_t _db = smT + _buf * TCHB;                                       \
        _Pragma("unroll")                                                       \
        for (int it = 0; it < 2; it++) {                                        \
            int id = tid + it * 128;                                            \
            int r = id >> 2, q = id & 3;                                        \
            cpasync16(_da + r * (AST * 2) + q * 16,                             \
                      A + (size_t)r * Nn + (kb) * 32 + q * 8);                  \
        }                                                                       \
        _Pragma("unroll")                                                       \
        for (int it = 0; it < 8; it++) {                                        \
            int id = tid + it * 128;                                            \
            int r = id >> 5, q = id & 31;                                       \
            uint32_t col = (uint32_t)(q * 16) ^ ((r & 7) << 4);                 \
            cpasync16(_db + r * 512 + col,                                      \
                      T + (size_t)((kb) * 32 + r) * Hh + q * 8);                \
        }                                                                       \
        asm volatile("cp.async.commit_group;" ::: "memory");                    \
    }

    AISSUE(0);
    AISSUE(1);

    for (int kb = 0; kb < 16; kb++) {
        if (kb == 15) asm volatile("cp.async.wait_group 0;" ::: "memory");
        else          asm volatile("cp.async.wait_group 1;" ::: "memory");
        __syncthreads();

        uint32_t aA = smA + (kb & 1) * ACHB;
        uint32_t aB = smT + (kb & 1) * TCHB;

#pragma unroll
        for (int ks = 0; ks < 2; ks++) {
            const int k0 = ks * 16;
            uint32_t af[4][4], bf[8][2];
#pragma unroll
            for (int mi = 0; mi < 4; mi++) {
                uint32_t ad = aA + (mi * 16 + a_row) * (AST * 2) + (k0 + a_kc) * 2;
                ldsm_x4(af[mi][0], af[mi][1], af[mi][2], af[mi][3], ad);
            }
#pragma unroll
            for (int nip = 0; nip < 4; nip++) {
                int krow = k0 + bt_kr;
                int ncol = n_off + nip * 16 + bt_nc;
                uint32_t bd = aB + krow * 512 + (((uint32_t)(ncol * 2)) ^ ((krow & 7) << 4));
                ldsm_x4_t(bf[nip * 2][0], bf[nip * 2][1], bf[nip * 2 + 1][0], bf[nip * 2 + 1][1], bd);
            }
#pragma unroll
            for (int mi = 0; mi < 4; mi++)
#pragma unroll
                for (int ni = 0; ni < 8; ni++)
                    mma_bf16(acc[mi][ni], af[mi], bf[ni]);
        }
        __syncthreads();
        if (kb + 2 < 16) AISSUE(kb + 2);
    }
#undef AISSUE

    // ---------- epilogue 1: bias + relu; pool or stage H to smem ----------
    float pl0[8], pl1[8];
#pragma unroll
    for (int ni = 0; ni < 8; ni++) { pl0[ni] = 0.f; pl1[ni] = 0.f; }

#pragma unroll
    for (int mi = 0; mi < 4; mi++) {
#pragma unroll
        for (int ni = 0; ni < 8; ni++) {
            int c = n_off + ni * 8 + tig * 2;
            float b0 = bias[c], b1 = bias[c + 1];
            float v0 = fmaxf(acc[mi][ni][0] + b0, 0.f);
            float v1 = fmaxf(acc[mi][ni][1] + b1, 0.f);
            float v2 = fmaxf(acc[mi][ni][2] + b0, 0.f);
            float v3 = fmaxf(acc[mi][ni][3] + b1, 0.f);
            pl0[ni] += v0 + v2;
            pl1[ni] += v1 + v3;
            __nv_bfloat162 p0 = __float22bfloat162_rn(make_float2(v0, v1));
            __nv_bfloat162 p1 = __float22bfloat162_rn(make_float2(v2, v3));
            // H[row][c] bf16 pairs at row*HST + c*2
            uint32_t h0 = smH + (mi * 16 + gid)     * HST + c * 2;
            uint32_t h1 = smH + (mi * 16 + gid + 8) * HST + c * 2;
            asm volatile("st.shared.b32 [%0], %1;" :: "r"(h0), "r"(*(uint32_t*)&p0) : "memory");
            asm volatile("st.shared.b32 [%0], %1;" :: "r"(h1), "r"(*(uint32_t*)&p1) : "memory");
        }
    }

    if (do_pool) {
#pragma unroll
        for (int ni = 0; ni < 8; ni++) {
            int c = n_off + ni * 8 + tig * 2;
            atomicAdd(&g_pool[task * Hh + c],     pl0[ni]);
            atomicAdd(&g_pool[task * Hh + c + 1], pl1[ni]);
        }
    }
    if (layer < 0) return;    // last layer: pool only

    __syncthreads();          // H visible to all warps

    // ---------- phase 2: T' = H @ W  (K = 256, 16 chunks of 16) ----------
    const __nv_bfloat16* W = g_Wtb + (size_t)layer * Hh * Hh;

#pragma unroll
    for (int mi = 0; mi < 4; mi++)
#pragma unroll
        for (int ni = 0; ni < 8; ni++)
#pragma unroll
            for (int q = 0; q < 4; q++) acc[mi][ni][q] = 0.f;

#define WISSUE(kc)                                                              \
    {                                                                           \
        uint32_t _dw = smW + ((kc) & 1) * WCH2;                                 \
        _Pragma("unroll")                                                       \
        for (int it = 0; it < 4; it++) {                                        \
            int id = tid + it * 128;                                            \
            int r = id >> 1, g = id & 1;                                        \
            cpasync16(_dw + r * WST + g * 16,                                   \
                      W + (size_t)r * Hh + (kc) * 16 + g * 8);                  \
        }                                                                       \
        asm volatile("cp.async.commit_group;" ::: "memory");                    \
    }

    WISSUE(0);
    WISSUE(1);

    for (int kc = 0; kc < 16; kc++) {
        if (kc == 15) asm volatile("cp.async.wait_group 0;" ::: "memory");
        else          asm volatile("cp.async.wait_group 1;" ::: "memory");
        __syncthreads();

        uint32_t aW = smW + (kc & 1) * WCH2;
        uint32_t af[4][4], bf[8][2];
#pragma unroll
        for (int mi = 0; mi < 4; mi++) {
            uint32_t ad = smH + (mi * 16 + a_row) * HST + (kc * 16 + a_kc) * 2;
            ldsm_x4(af[mi][0], af[mi][1], af[mi][2], af[mi][3], ad);
        }
#pragma unroll
        for (int nip = 0; nip < 4; nip++) {
            uint32_t bd = aW + (n_off + nip * 16 + b_row) * WST + b_kc * 2;
            ldsm_x4(bf[nip * 2][0], bf[nip * 2][1], bf[nip * 2 + 1][0], bf[nip * 2 + 1][1], bd);
        }
#pragma unroll
        for (int mi = 0; mi < 4; mi++)
#pragma unroll
            for (int ni = 0; ni < 8; ni++)
                mma_bf16(acc[mi][ni], af[mi], bf[ni]);

        __syncthreads();
        if (kc + 2 < 16) WISSUE(kc + 2);
    }
#undef WISSUE

    // ---------- epilogue 2: pack T' pairs ----------
#pragma unroll
    for (int mi = 0; mi < 4; mi++) {
        int r0 = mi * 16 + gid;
#pragma unroll
        for (int ni = 0; ni < 8; ni++) {
            int pi = n_off / 2 + ni * 4 + tig;
            __nv_bfloat162 p0 = __float22bfloat162_rn(make_float2(acc[mi][ni][0], acc[mi][ni][1]));
            __nv_bfloat162 p1 = __float22bfloat162_rn(make_float2(acc[mi][ni][2], acc[mi][ni][3]));
            Co[(size_t)r0 * HP + pi]       = *reinterpret_cast<uint32_t*>(&p0);
            Co[(size_t)(r0 + 8) * HP + pi] = *reinterpret_cast<uint32_t*>(&p1);
        }
    }
}

// ---------------- FC head (pool scale folded in) ----------------
__global__ void fck(const float* __restrict__ hfeat, const float* __restrict__ afeat,
                    const float* __restrict__ fcW, const float* __restrict__ fcb,
                    float* __restrict__ out) {
    int g = blockIdx.x;
    int c = threadIdx.x >> 5;
    int lane = threadIdx.x & 31;
    const float ps = 1.0f / Nn;
    float acc = 0.f;
    for (int i = lane; i < 2 * (Hh + 6); i += 32) {
        float xv;
        if      (i < 256) xv = g_pool[g * Hh + i] * ps;
        else if (i < 262) xv = hfeat[g * 6 + (i - 256)];
        else if (i < 518) xv = g_pool[(Gn + g) * Hh + (i - 262)] * ps;
        else              xv = afeat[g * 6 + (i - 518)];
        acc += xv * fcW[i * 3 + c];
    }
#pragma unroll
    for (int o = 16; o; o >>= 1) acc += __shfl_down_sync(0xffffffff, acc, o);
    if (lane == 0) out[g * 3 + c] = acc + fcb[c];
}

// ---------------- launch ----------------
extern "C" void kernel_launch(void* const* d_in, const int* in_sizes, int n_in,
                              void* d_out, int out_size) {
    const float* home_x = (const float*)d_in[0];
    const float* away_x = (const float*)d_in[1];
    const int*   hei    = (const int*)d_in[2];
    const int*   aei    = (const int*)d_in[3];
    const float* hew    = (const float*)d_in[4];
    const float* aew    = (const float*)d_in[5];
    const float* hfeat  = (const float*)d_in[6];
    const float* afeat  = (const float*)d_in[7];
    const float* W0     = (const float*)d_in[8];
    const float* Wh     = (const float*)d_in[9];
    const float* bs     = (const float*)d_in[10];
    const float* fcW    = (const float*)d_in[11];
    const float* fcb    = (const float*)d_in[12];
    float* out = (float*)d_out;

    cudaFuncSetAttribute(layer_fused, cudaFuncAttributeMaxDynamicSharedMemorySize, FUS_SMEM);

    // prep: dinv/selfnorm, fused zero+build dense adjacency (L2-resident), bf16 weights
    prep_init<<<TASKS * Hh / 256, 256>>>();
    prep_degree<<<TASKS, 512>>>(hei, aei, hew, aew);
    build_Ad3<<<BAD_CTAS, 512>>>(hei, aei, hew, aew);
    wt_prep<<<dim3(Hh, 4), Hh>>>(Wh);

    // layer 0 input transform
    gemm0<<<dim3(TASKS, Nn / 8), 128>>>(home_x, away_x, W0);

    // 5 fused GCN layers: agg (+relu+bias) then feature GEMM of NEXT layer
    for (int l = 0; l < 5; l++) {
        layer_fused<<<dim3(8, TASKS), 128, FUS_SMEM>>>(
            l & 1,                 // T in/out ping-pong
            (l < 4) ? l : -1,      // weight index for phase 2; -1 = pool-only
            bs + l * Hh,
            (l == 4) ? 1 : 0);
    }

    // head
    fck<<<Gn, 96>>>(hfeat, afeat, fcW, fcb, out);
}

// round 15
// speedup vs baseline: 1.1006x; 1.1006x over previous
#include <cuda_runtime.h>
#include <cuda_bf16.h>
#include <math.h>
#include <stdint.h>

#define Gn   256      // graphs
#define Nn   512      // nodes per graph
#define En   16384    // edges per graph
#define Hh   256      // hidden
#define FIN  4
#define TASKS 512     // 256 home + 256 away
#define HP   128      // Hh/2 pairs

// ---------------- scratch (device globals; no allocation) ----------------
__device__ __align__(16) uint32_t      g_C [(size_t)TASKS * Nn * HP];  // T ping
__device__ __align__(16) uint32_t      g_C2[(size_t)TASKS * Nn * HP];  // T pong
__device__ __align__(16) __nv_bfloat16 g_Ad[(size_t)TASKS * Nn * Nn]; // dense normalized adjacency
__device__ float g_dinv[TASKS * Nn];
__device__ float g_selfnorm[TASKS * Nn];
__device__ float g_pool[TASKS * Hh];
__device__ __nv_bfloat16 g_Wtb[4 * Hh * Hh];                // bf16 weights, [l][n][k]

__device__ __forceinline__ uint32_t smem_u32(const void* p) {
    uint32_t a;
    asm("{ .reg .u64 t; cvta.to.shared.u64 t, %1; cvt.u32.u64 %0, t; }" : "=r"(a) : "l"(p));
    return a;
}
__device__ __forceinline__ void cpasync16(uint32_t dst, const void* src) {
    asm volatile("cp.async.cg.shared.global [%0], [%1], 16;" :: "r"(dst), "l"(src) : "memory");
}
__device__ __forceinline__ void ldsm_x4(uint32_t& r0, uint32_t& r1, uint32_t& r2, uint32_t& r3,
                                        uint32_t addr) {
    asm volatile("ldmatrix.sync.aligned.m8n8.x4.shared.b16 {%0,%1,%2,%3}, [%4];"
                 : "=r"(r0), "=r"(r1), "=r"(r2), "=r"(r3) : "r"(addr));
}
__device__ __forceinline__ void ldsm_x4_t(uint32_t& r0, uint32_t& r1, uint32_t& r2, uint32_t& r3,
                                          uint32_t addr) {
    asm volatile("ldmatrix.sync.aligned.m8n8.x4.trans.shared.b16 {%0,%1,%2,%3}, [%4];"
                 : "=r"(r0), "=r"(r1), "=r"(r2), "=r"(r3) : "r"(addr));
}
__device__ __forceinline__ void mma_bf16(float* c, const uint32_t* a, const uint32_t* b) {
    asm volatile(
        "mma.sync.aligned.m16n8k16.row.col.f32.bf16.bf16.f32 "
        "{%0,%1,%2,%3}, {%4,%5,%6,%7}, {%8,%9}, {%0,%1,%2,%3};"
        : "+f"(c[0]), "+f"(c[1]), "+f"(c[2]), "+f"(c[3])
        : "r"(a[0]), "r"(a[1]), "r"(a[2]), "r"(a[3]), "r"(b[0]), "r"(b[1]));
}

// ---------------- prep: degree -> dinv/selfnorm (smem histogram) ----------------
__global__ void prep_init() {                  // zero pool
    g_pool[blockIdx.x * 256 + threadIdx.x] = 0.0f;
}

__global__ __launch_bounds__(512) void prep_degree(
        const int* __restrict__ hei, const int* __restrict__ aei,
        const float* __restrict__ hew, const float* __restrict__ aew) {
    __shared__ float sdeg[Nn];
    int task = blockIdx.x, tid = threadIdx.x;
    sdeg[tid] = 1.0f;      // self-loop weight
    __syncthreads();
    const int*   ei = (task < Gn) ? hei + (size_t)task * 2 * En : aei + (size_t)(task - Gn) * 2 * En;
    const float* ew = (task < Gn) ? hew + (size_t)task * En     : aew + (size_t)(task - Gn) * En;
#pragma unroll 4
    for (int it = 0; it < En / 512; it++) {
        int e = it * 512 + tid;
        atomicAdd(&sdeg[ei[En + e]], ew[e]);
    }
    __syncthreads();
    float di = rsqrtf(sdeg[tid]);
    g_dinv[task * Nn + tid] = di;
    g_selfnorm[task * Nn + tid] = di * di;
}

// ---------------- fused dense adjacency build: zero + scatter, L2-resident (r12 WIN) ----------------
#define BAD_CTAS 128

__global__ __launch_bounds__(512) void build_Ad3(
        const int* __restrict__ hei, const int* __restrict__ aei,
        const float* __restrict__ hew, const float* __restrict__ aew) {
    __shared__ float sdinv[Nn];
    const int tid = threadIdx.x;

    for (int task = blockIdx.x; task < TASKS; task += BAD_CTAS) {
        __nv_bfloat16* Ad = g_Ad + (size_t)task * Nn * Nn;

        for (int i = tid; i < Nn * Nn / 8; i += 512)
            ((uint4*)Ad)[i] = make_uint4(0, 0, 0, 0);
        sdinv[tid] = g_dinv[task * Nn + tid];
        __syncthreads();

        const int*   ei = (task < Gn) ? hei + (size_t)task * 2 * En
                                      : aei + (size_t)(task - Gn) * 2 * En;
        const float* ew = (task < Gn) ? hew + (size_t)task * En
                                      : aew + (size_t)(task - Gn) * En;
#pragma unroll 4
        for (int it = 0; it < En / 512; it++) {
            int e = it * 512 + tid;
            int s = ei[e];
            int t = ei[En + e];
            float norm = sdinv[s] * ew[e] * sdinv[t];
            atomicAdd(Ad + (size_t)t * Nn + s, __float2bfloat16(norm));
        }
        atomicAdd(Ad + (size_t)tid * Nn + tid, __float2bfloat16(g_selfnorm[task * Nn + tid]));
        __syncthreads();
    }
}

// ---------------- weight prep: Wtb[l][n][k] = bf16(Wh[l][k][n]) ----------------
__global__ void wt_prep(const float* __restrict__ Wh) {
    int l = blockIdx.y, n = blockIdx.x, k = threadIdx.x;
    g_Wtb[(size_t)l * Hh * Hh + (size_t)n * Hh + k] =
        __float2bfloat16(Wh[(size_t)l * Hh * Hh + (size_t)k * Hh + n]);
}

// ---------------- layer 0 GEMM: C = X[512,4] @ W0[4,256], bf16-pair out ----------------
__global__ void gemm0(const float* __restrict__ hx, const float* __restrict__ ax,
                      const float* __restrict__ W0) {
    int task = blockIdx.x;
    int n0 = blockIdx.y * 8;
    int h = threadIdx.x;     // pair index 0..127
    const float* x = (task < Gn) ? hx + (size_t)task * Nn * FIN
                                 : ax + (size_t)(task - Gn) * Nn * FIN;
    float wa0 = W0[2 * h],            wb0 = W0[2 * h + 1];
    float wa1 = W0[Hh + 2 * h],       wb1 = W0[Hh + 2 * h + 1];
    float wa2 = W0[2 * Hh + 2 * h],   wb2 = W0[2 * Hh + 2 * h + 1];
    float wa3 = W0[3 * Hh + 2 * h],   wb3 = W0[3 * Hh + 2 * h + 1];
    uint32_t* C = g_C + (size_t)task * Nn * HP;
#pragma unroll
    for (int i = 0; i < 8; i++) {
        int n = n0 + i;
        float4 xv = *(const float4*)(x + n * 4);
        float c0 = xv.x * wa0 + xv.y * wa1 + xv.z * wa2 + xv.w * wa3;
        float c1 = xv.x * wb0 + xv.y * wb1 + xv.z * wb2 + xv.w * wb3;
        __nv_bfloat162 p = __float22bfloat162_rn(make_float2(c0, c1));
        C[n * HP + h] = *reinterpret_cast<uint32_t*>(&p);
    }
}

// ---------------- fused GCN layer v2: smem phases aliased -> 58KB -> 2 CTAs/SM ----------------
// CTA: 64 rows x 256 channels; grid (8 m-blocks, TASKS), 128 threads = 4 warps (1m x 4n).
// Phase 1 region: [A0 A1 | T0 T1] = 43008 B at sm0.
// Phase 2 region: [H (33792) | W0 W1 (24576)] = 58368 B at sm0 (aliases phase 1 — dead by then).
#define AST  40
#define ACHB (64 * AST * 2)      // 5120
#define TCHB 16384
#define HST  528                 // H row stride (33x16B units, odd -> conflict-free)
#define HSZ  (64 * HST)          // 33792
#define WST  48                  // W chunk row stride (3x16B)
#define WCH2 (256 * WST)         // 12288
#define PH2_SZ (HSZ + 2 * WCH2)  // 58368
#define FUS_SMEM PH2_SZ          // > 2*ACHB+2*TCHB = 43008

__global__ __launch_bounds__(128) void layer_fused(int bufsel, int layer,
                                                   const float* __restrict__ bias, int do_pool) {
    extern __shared__ __align__(128) char smg[];
    const uint32_t sm0 = smem_u32(smg);
    const uint32_t smA = sm0;                       // phase 1: 2 x ACHB
    const uint32_t smT = sm0 + 2 * ACHB;            // phase 1: 2 x TCHB
    const uint32_t smH = sm0;                       // phase 2: aliases phase-1 region
    const uint32_t smW = sm0 + HSZ;                 // phase 2: 2 x WCH2

    const int task = blockIdx.y;
    const int bm = blockIdx.x * 64;
    const uint32_t* Tin  = bufsel ? g_C2 : g_C;
    uint32_t*       Tout = bufsel ? g_C  : g_C2;
    const __nv_bfloat16* A = g_Ad + (size_t)task * Nn * Nn + (size_t)bm * Nn;
    const __nv_bfloat16* T = (const __nv_bfloat16*)(Tin + (size_t)task * Nn * HP);
    uint32_t* Co = Tout + (size_t)task * Nn * HP + (size_t)bm * HP;

    const int tid  = threadIdx.x;
    const int lane = tid & 31;
    const int wid  = tid >> 5;
    const int n_off = wid * 64;
    const int gid = lane >> 2;
    const int tig = lane & 3;

    const int a_row = (lane & 15);
    const int a_kc  = (lane >> 4) * 8;
    const int b_row = (lane & 7) + (lane >> 4) * 8;
    const int b_kc  = ((lane >> 3) & 1) * 8;
    const int bt_kr = (lane & 15);
    const int bt_nc = (lane >> 4) * 8;

    float acc[4][8][4];
#pragma unroll
    for (int mi = 0; mi < 4; mi++)
#pragma unroll
        for (int ni = 0; ni < 8; ni++)
#pragma unroll
            for (int q = 0; q < 4; q++) acc[mi][ni][q] = 0.f;

    // ---------- phase 1: Ahat @ T ----------
#define AISSUE(kb)                                                              \
    {                                                                           \
        int _buf = (kb) & 1;                                                    \
        uint32_t _da = smA + _buf * ACHB;                                       \
        uint32_t _db = smT + _buf * TCHB;                                       \
        _Pragma("unroll")                                                       \
        for (int it = 0; it < 2; it++) {                                        \
            int id = tid + it * 128;                                            \
            int r = id >> 2, q = id & 3;                                        \
            cpasync16(_da + r * (AST * 2) + q * 16,                             \
                      A + (size_t)r * Nn + (kb) * 32 + q * 8);                  \
        }                                                                       \
        _Pragma("unroll")                                                       \
        for (int it = 0; it < 8; it++) {                                        \
            int id = tid + it * 128;                                            \
            int r = id >> 5, q = id & 31;                                       \
            uint32_t col = (uint32_t)(q * 16) ^ ((r & 7) << 4);                 \
            cpasync16(_db + r * 512 + col,                                      \
                      T + (size_t)((kb) * 32 + r) * Hh + q * 8);                \
        }                                                                       \
        asm volatile("cp.async.commit_group;" ::: "memory");                    \
    }

    AISSUE(0);
    AISSUE(1);

    for (int kb = 0; kb < 16; kb++) {
        if (kb == 15) asm volatile("cp.async.wait_group 0;" ::: "memory");
        else          asm volatile("cp.async.wait_group 1;" ::: "memory");
        __syncthreads();

        uint32_t aA = smA + (kb & 1) * ACHB;
        uint32_t aB = smT + (kb & 1) * TCHB;

#pragma unroll
        for (int ks = 0; ks < 2; ks++) {
            const int k0 = ks * 16;
            uint32_t af[4][4], bf[8][2];
#pragma unroll
            for (int mi = 0; mi < 4; mi++) {
                uint32_t ad = aA + (mi * 16 + a_row) * (AST * 2) + (k0 + a_kc) * 2;
                ldsm_x4(af[mi][0], af[mi][1], af[mi][2], af[mi][3], ad);
            }
#pragma unroll
            for (int nip = 0; nip < 4; nip++) {
                int krow = k0 + bt_kr;
                int ncol = n_off + nip * 16 + bt_nc;
                uint32_t bd = aB + krow * 512 + (((uint32_t)(ncol * 2)) ^ ((krow & 7) << 4));
                ldsm_x4_t(bf[nip * 2][0], bf[nip * 2][1], bf[nip * 2 + 1][0], bf[nip * 2 + 1][1], bd);
            }
#pragma unroll
            for (int mi = 0; mi < 4; mi++)
#pragma unroll
                for (int ni = 0; ni < 8; ni++)
                    mma_bf16(acc[mi][ni], af[mi], bf[ni]);
        }
        __syncthreads();   // final iteration: all phase-1 smem reads complete after this
        if (kb + 2 < 16) AISSUE(kb + 2);
    }
#undef AISSUE

    // ---------- epilogue 1: bias + relu; pool; stage H to smem (aliases dead phase-1 bufs) ----------
    float pl0[8], pl1[8];
#pragma unroll
    for (int ni = 0; ni < 8; ni++) { pl0[ni] = 0.f; pl1[ni] = 0.f; }

#pragma unroll
    for (int mi = 0; mi < 4; mi++) {
#pragma unroll
        for (int ni = 0; ni < 8; ni++) {
            int c = n_off + ni * 8 + tig * 2;
            float b0 = bias[c], b1 = bias[c + 1];
            float v0 = fmaxf(acc[mi][ni][0] + b0, 0.f);
            float v1 = fmaxf(acc[mi][ni][1] + b1, 0.f);
            float v2 = fmaxf(acc[mi][ni][2] + b0, 0.f);
            float v3 = fmaxf(acc[mi][ni][3] + b1, 0.f);
            pl0[ni] += v0 + v2;
            pl1[ni] += v1 + v3;
            __nv_bfloat162 p0 = __float22bfloat162_rn(make_float2(v0, v1));
            __nv_bfloat162 p1 = __float22bfloat162_rn(make_float2(v2, v3));
            uint32_t h0 = smH + (mi * 16 + gid)     * HST + c * 2;
            uint32_t h1 = smH + (mi * 16 + gid + 8) * HST + c * 2;
            asm volatile("st.shared.b32 [%0], %1;" :: "r"(h0), "r"(*(uint32_t*)&p0) : "memory");
            asm volatile("st.shared.b32 [%0], %1;" :: "r"(h1), "r"(*(uint32_t*)&p1) : "memory");
        }
    }

    if (do_pool) {
#pragma unroll
        for (int ni = 0; ni < 8; ni++) {
            int c = n_off + ni * 8 + tig * 2;
            atomicAdd(&g_pool[task * Hh + c],     pl0[ni]);
            atomicAdd(&g_pool[task * Hh + c + 1], pl1[ni]);
        }
    }
    if (layer < 0) return;    // last layer: pool only

    __syncthreads();          // H visible to all warps

    // ---------- phase 2: T' = H @ W  (K = 256, 16 chunks of 16) ----------
    const __nv_bfloat16* W = g_Wtb + (size_t)layer * Hh * Hh;

#pragma unroll
    for (int mi = 0; mi < 4; mi++)
#pragma unroll
        for (int ni = 0; ni < 8; ni++)
#pragma unroll
            for (int q = 0; q < 4; q++) acc[mi][ni][q] = 0.f;

#define WISSUE(kc)                                                              \
    {                                                                           \
        uint32_t _dw = smW + ((kc) & 1) * WCH2;                                 \
        _Pragma("unroll")                                                       \
        for (int it = 0; it < 4; it++) {                                        \
            int id = tid + it * 128;                                            \
            int r = id >> 1, g = id & 1;                                        \
            cpasync16(_dw + r * WST + g * 16,                                   \
                      W + (size_t)r * Hh + (kc) * 16 + g * 8);                  \
        }                                                                       \
        asm volatile("cp.async.commit_group;" ::: "memory");                    \
    }

    WISSUE(0);
    WISSUE(1);

    for (int kc = 0; kc < 16; kc++) {
        if (kc == 15) asm volatile("cp.async.wait_group 0;" ::: "memory");
        else          asm volatile("cp.async.wait_group 1;" ::: "memory");
        __syncthreads();

        uint32_t aW = smW + (kc & 1) * WCH2;
        uint32_t af[4][4], bf[8][2];
#pragma unroll
        for (int mi = 0; mi < 4; mi++) {
            uint32_t ad = smH + (mi * 16 + a_row) * HST + (kc * 16 + a_kc) * 2;
            ldsm_x4(af[mi][0], af[mi][1], af[mi][2], af[mi][3], ad);
        }
#pragma unroll
        for (int nip = 0; nip < 4; nip++) {
            uint32_t bd = aW + (n_off + nip * 16 + b_row) * WST + b_kc * 2;
            ldsm_x4(bf[nip * 2][0], bf[nip * 2][1], bf[nip * 2 + 1][0], bf[nip * 2 + 1][1], bd);
        }
#pragma unroll
        for (int mi = 0; mi < 4; mi++)
#pragma unroll
            for (int ni = 0; ni < 8; ni++)
                mma_bf16(acc[mi][ni], af[mi], bf[ni]);

        __syncthreads();
        if (kc + 2 < 16) WISSUE(kc + 2);
    }
#undef WISSUE

    // ---------- epilogue 2: pack T' pairs ----------
#pragma unroll
    for (int mi = 0; mi < 4; mi++) {
        int r0 = mi * 16 + gid;
#pragma unroll
        for (int ni = 0; ni < 8; ni++) {
            int pi = n_off / 2 + ni * 4 + tig;
            __nv_bfloat162 p0 = __float22bfloat162_rn(make_float2(acc[mi][ni][0], acc[mi][ni][1]));
            __nv_bfloat162 p1 = __float22bfloat162_rn(make_float2(acc[mi][ni][2], acc[mi][ni][3]));
            Co[(size_t)r0 * HP + pi]       = *reinterpret_cast<uint32_t*>(&p0);
            Co[(size_t)(r0 + 8) * HP + pi] = *reinterpret_cast<uint32_t*>(&p1);
        }
    }
}

// ---------------- FC head (pool scale folded in) ----------------
__global__ void fck(const float* __restrict__ hfeat, const float* __restrict__ afeat,
                    const float* __restrict__ fcW, const float* __restrict__ fcb,
                    float* __restrict__ out) {
    int g = blockIdx.x;
    int c = threadIdx.x >> 5;
    int lane = threadIdx.x & 31;
    const float ps = 1.0f / Nn;
    float acc = 0.f;
    for (int i = lane; i < 2 * (Hh + 6); i += 32) {
        float xv;
        if      (i < 256) xv = g_pool[g * Hh + i] * ps;
        else if (i < 262) xv = hfeat[g * 6 + (i - 256)];
        else if (i < 518) xv = g_pool[(Gn + g) * Hh + (i - 262)] * ps;
        else              xv = afeat[g * 6 + (i - 518)];
        acc += xv * fcW[i * 3 + c];
    }
#pragma unroll
    for (int o = 16; o; o >>= 1) acc += __shfl_down_sync(0xffffffff, acc, o);
    if (lane == 0) out[g * 3 + c] = acc + fcb[c];
}

// ---------------- launch ----------------
extern "C" void kernel_launch(void* const* d_in, const int* in_sizes, int n_in,
                              void* d_out, int out_size) {
    const float* home_x = (const float*)d_in[0];
    const float* away_x = (const float*)d_in[1];
    const int*   hei    = (const int*)d_in[2];
    const int*   aei    = (const int*)d_in[3];
    const float* hew    = (const float*)d_in[4];
    const float* aew    = (const float*)d_in[5];
    const float* hfeat  = (const float*)d_in[6];
    const float* afeat  = (const float*)d_in[7];
    const float* W0     = (const float*)d_in[8];
    const float* Wh     = (const float*)d_in[9];
    const float* bs     = (const float*)d_in[10];
    const float* fcW    = (const float*)d_in[11];
    const float* fcb    = (const float*)d_in[12];
    float* out = (float*)d_out;

    cudaFuncSetAttribute(layer_fused, cudaFuncAttributeMaxDynamicSharedMemorySize, FUS_SMEM);

    // prep: dinv/selfnorm, fused zero+build dense adjacency (L2-resident), bf16 weights
    prep_init<<<TASKS * Hh / 256, 256>>>();
    prep_degree<<<TASKS, 512>>>(hei, aei, hew, aew);
    build_Ad3<<<BAD_CTAS, 512>>>(hei, aei, hew, aew);
    wt_prep<<<dim3(Hh, 4), Hh>>>(Wh);

    // layer 0 input transform
    gemm0<<<dim3(TASKS, Nn / 8), 128>>>(home_x, away_x, W0);

    // 5 fused GCN layers: agg (+relu+bias) then feature GEMM of NEXT layer
    for (int l = 0; l < 5; l++) {
        layer_fused<<<dim3(8, TASKS), 128, FUS_SMEM>>>(
            l & 1,                 // T in/out ping-pong
            (l < 4) ? l : -1,      // weight index for phase 2; -1 = pool-only
            bs + l * Hh,
            (l == 4) ? 1 : 0);
    }

    // head
    fck<<<Gn, 96>>>(hfeat, afeat, fcW, fcb, out);
}

// round 17
// speedup vs baseline: 1.1888x; 1.0801x over previous
#include <cuda_runtime.h>
#include <cuda_bf16.h>
#include <math.h>
#include <stdint.h>

#define Gn   256      // graphs
#define Nn   512      // nodes per graph
#define En   16384    // edges per graph
#define Hh   256      // hidden
#define FIN  4
#define TASKS 512     // 256 home + 256 away
#define HP   128      // Hh/2 pairs

// ---------------- scratch (device globals; no allocation) ----------------
__device__ __align__(16) uint32_t      g_C [(size_t)TASKS * Nn * HP];  // T ping
__device__ __align__(16) uint32_t      g_C2[(size_t)TASKS * Nn * HP];  // T pong
__device__ __align__(16) __nv_bfloat16 g_Ad[(size_t)TASKS * Nn * Nn]; // dense normalized adjacency
__device__ float g_dinv[TASKS * Nn];
__device__ float g_selfnorm[TASKS * Nn];
__device__ float g_pool[TASKS * Hh];
__device__ __nv_bfloat16 g_Wtb[4 * Hh * Hh];                // bf16 weights, [l][n][k]

__device__ __forceinline__ uint32_t smem_u32(const void* p) {
    uint32_t a;
    asm("{ .reg .u64 t; cvta.to.shared.u64 t, %1; cvt.u32.u64 %0, t; }" : "=r"(a) : "l"(p));
    return a;
}
__device__ __forceinline__ void cpasync16(uint32_t dst, const void* src) {
    asm volatile("cp.async.cg.shared.global [%0], [%1], 16;" :: "r"(dst), "l"(src) : "memory");
}
__device__ __forceinline__ void ldsm_x4(uint32_t& r0, uint32_t& r1, uint32_t& r2, uint32_t& r3,
                                        uint32_t addr) {
    asm volatile("ldmatrix.sync.aligned.m8n8.x4.shared.b16 {%0,%1,%2,%3}, [%4];"
                 : "=r"(r0), "=r"(r1), "=r"(r2), "=r"(r3) : "r"(addr));
}
__device__ __forceinline__ void ldsm_x4_t(uint32_t& r0, uint32_t& r1, uint32_t& r2, uint32_t& r3,
                                          uint32_t addr) {
    asm volatile("ldmatrix.sync.aligned.m8n8.x4.trans.shared.b16 {%0,%1,%2,%3}, [%4];"
                 : "=r"(r0), "=r"(r1), "=r"(r2), "=r"(r3) : "r"(addr));
}
__device__ __forceinline__ void mma_bf16(float* c, const uint32_t* a, const uint32_t* b) {
    asm volatile(
        "mma.sync.aligned.m16n8k16.row.col.f32.bf16.bf16.f32 "
        "{%0,%1,%2,%3}, {%4,%5,%6,%7}, {%8,%9}, {%0,%1,%2,%3};"
        : "+f"(c[0]), "+f"(c[1]), "+f"(c[2]), "+f"(c[3])
        : "r"(a[0]), "r"(a[1]), "r"(a[2]), "r"(a[3]), "r"(b[0]), "r"(b[1]));
}

// ---------------- prep: degree -> dinv/selfnorm (smem histogram) ----------------
__global__ void prep_init() {                  // zero pool
    g_pool[blockIdx.x * 256 + threadIdx.x] = 0.0f;
}

__global__ __launch_bounds__(512) void prep_degree(
        const int* __restrict__ hei, const int* __restrict__ aei,
        const float* __restrict__ hew, const float* __restrict__ aew) {
    __shared__ float sdeg[Nn];
    int task = blockIdx.x, tid = threadIdx.x;
    sdeg[tid] = 1.0f;      // self-loop weight
    __syncthreads();
    const int*   ei = (task < Gn) ? hei + (size_t)task * 2 * En : aei + (size_t)(task - Gn) * 2 * En;
    const float* ew = (task < Gn) ? hew + (size_t)task * En     : aew + (size_t)(task - Gn) * En;
#pragma unroll 4
    for (int it = 0; it < En / 512; it++) {
        int e = it * 512 + tid;
        atomicAdd(&sdeg[ei[En + e]], ew[e]);
    }
    __syncthreads();
    float di = rsqrtf(sdeg[tid]);
    g_dinv[task * Nn + tid] = di;
    g_selfnorm[task * Nn + tid] = di * di;
}

// ---------------- fused dense adjacency build: zero + scatter, L2-resident (r12 WIN) ----------------
#define BAD_CTAS 128

__global__ __launch_bounds__(512) void build_Ad3(
        const int* __restrict__ hei, const int* __restrict__ aei,
        const float* __restrict__ hew, const float* __restrict__ aew) {
    __shared__ float sdinv[Nn];
    const int tid = threadIdx.x;

    for (int task = blockIdx.x; task < TASKS; task += BAD_CTAS) {
        __nv_bfloat16* Ad = g_Ad + (size_t)task * Nn * Nn;

        for (int i = tid; i < Nn * Nn / 8; i += 512)
            ((uint4*)Ad)[i] = make_uint4(0, 0, 0, 0);
        sdinv[tid] = g_dinv[task * Nn + tid];
        __syncthreads();

        const int*   ei = (task < Gn) ? hei + (size_t)task * 2 * En
                                      : aei + (size_t)(task - Gn) * 2 * En;
        const float* ew = (task < Gn) ? hew + (size_t)task * En
                                      : aew + (size_t)(task - Gn) * En;
#pragma unroll 4
        for (int it = 0; it < En / 512; it++) {
            int e = it * 512 + tid;
            int s = ei[e];
            int t = ei[En + e];
            float norm = sdinv[s] * ew[e] * sdinv[t];
            atomicAdd(Ad + (size_t)t * Nn + s, __float2bfloat16(norm));
        }
        atomicAdd(Ad + (size_t)tid * Nn + tid, __float2bfloat16(g_selfnorm[task * Nn + tid]));
        __syncthreads();
    }
}

// ---------------- weight prep: Wtb[l][n][k] = bf16(Wh[l][k][n]) ----------------
__global__ void wt_prep(const float* __restrict__ Wh) {
    int l = blockIdx.y, n = blockIdx.x, k = threadIdx.x;
    g_Wtb[(size_t)l * Hh * Hh + (size_t)n * Hh + k] =
        __float2bfloat16(Wh[(size_t)l * Hh * Hh + (size_t)k * Hh + n]);
}

// ---------------- layer 0 GEMM: C = X[512,4] @ W0[4,256], bf16-pair out ----------------
__global__ void gemm0(const float* __restrict__ hx, const float* __restrict__ ax,
                      const float* __restrict__ W0) {
    int task = blockIdx.x;
    int n0 = blockIdx.y * 8;
    int h = threadIdx.x;     // pair index 0..127
    const float* x = (task < Gn) ? hx + (size_t)task * Nn * FIN
                                 : ax + (size_t)(task - Gn) * Nn * FIN;
    float wa0 = W0[2 * h],            wb0 = W0[2 * h + 1];
    float wa1 = W0[Hh + 2 * h],       wb1 = W0[Hh + 2 * h + 1];
    float wa2 = W0[2 * Hh + 2 * h],   wb2 = W0[2 * Hh + 2 * h + 1];
    float wa3 = W0[3 * Hh + 2 * h],   wb3 = W0[3 * Hh + 2 * h + 1];
    uint32_t* C = g_C + (size_t)task * Nn * HP;
#pragma unroll
    for (int i = 0; i < 8; i++) {
        int n = n0 + i;
        float4 xv = *(const float4*)(x + n * 4);
        float c0 = xv.x * wa0 + xv.y * wa1 + xv.z * wa2 + xv.w * wa3;
        float c1 = xv.x * wb0 + xv.y * wb1 + xv.z * wb2 + xv.w * wb3;
        __nv_bfloat162 p = __float22bfloat162_rn(make_float2(c0, c1));
        C[n * HP + h] = *reinterpret_cast<uint32_t*>(&p);
    }
}

// ---------------- fused GCN layer v3 (FIXED smem sizing): depth-3 phase 1, k=32 phase 2 ----------------
// CTA: 64 rows x 256 channels; grid (8 m-blocks, TASKS), 128 threads = 4 warps (1m x 4n).
// Phase 1 region: [A0 A1 A2 | T0 T1 T2] = 64512 B at sm0 (depth 3).
// Phase 2 region: [H (33792) | W0 W1 (2 x 20480)] = 74752 B at sm0 (aliases dead phase 1).
#define AST  40
#define ACHB (64 * AST * 2)      // 5120
#define TCHB 16384
#define HST  528                 // H row stride (33x16B units, odd -> conflict-free)
#define HSZ  (64 * HST)          // 33792
#define WCH2 (256 * AST * 2)     // 20480: W chunk [256n][32k] at 80B stride  (r16 bug: was /2)
#define FUS_SMEM (HSZ + 2 * WCH2)   // 74752 >= 3*ACHB+3*TCHB = 64512

__global__ __launch_bounds__(128) void layer_fused(int bufsel, int layer,
                                                   const float* __restrict__ bias, int do_pool) {
    extern __shared__ __align__(128) char smg[];
    const uint32_t sm0 = smem_u32(smg);
    const uint32_t smA = sm0;                       // phase 1: 3 x ACHB
    const uint32_t smT = sm0 + 3 * ACHB;            // phase 1: 3 x TCHB (ends 64512 < 74752)
    const uint32_t smH = sm0;                       // phase 2: aliases phase-1 region
    const uint32_t smW = sm0 + HSZ;                 // phase 2: 2 x WCH2 (ends 74752)

    const int task = blockIdx.y;
    const int bm = blockIdx.x * 64;
    const uint32_t* Tin  = bufsel ? g_C2 : g_C;
    uint32_t*       Tout = bufsel ? g_C  : g_C2;
    const __nv_bfloat16* A = g_Ad + (size_t)task * Nn * Nn + (size_t)bm * Nn;
    const __nv_bfloat16* T = (const __nv_bfloat16*)(Tin + (size_t)task * Nn * HP);
    uint32_t* Co = Tout + (size_t)task * Nn * HP + (size_t)bm * HP;

    const int tid  = threadIdx.x;
    const int lane = tid & 31;
    const int wid  = tid >> 5;
    const int n_off = wid * 64;
    const int gid = lane >> 2;
    const int tig = lane & 3;

    const int a_row = (lane & 15);
    const int a_kc  = (lane >> 4) * 8;
    const int b_row = (lane & 7) + (lane >> 4) * 8;
    const int b_kc  = ((lane >> 3) & 1) * 8;
    const int bt_kr = (lane & 15);
    const int bt_nc = (lane >> 4) * 8;

    float acc[4][8][4];
#pragma unroll
    for (int mi = 0; mi < 4; mi++)
#pragma unroll
        for (int ni = 0; ni < 8; ni++)
#pragma unroll
            for (int q = 0; q < 4; q++) acc[mi][ni][q] = 0.f;

    // ---------- phase 1: Ahat @ T (16 k-chunks of 32, pipeline depth 3) ----------
#define AISSUE(kb)                                                              \
    {                                                                           \
        int _buf = (kb) % 3;                                                    \
        uint32_t _da = smA + _buf * ACHB;                                       \
        uint32_t _db = smT + _buf * TCHB;                                       \
        _Pragma("unroll")                                                       \
        for (int it = 0; it < 2; it++) {                                        \
            int id = tid + it * 128;                                            \
            int r = id >> 2, q = id & 3;                                        \
            cpasync16(_da + r * (AST * 2) + q * 16,                             \
                      A + (size_t)r * Nn + (kb) * 32 + q * 8);                  \
        }                                                                       \
        _Pragma("unroll")                                                       \
        for (int it = 0; it < 8; it++) {                                        \
            int id = tid + it * 128;                                            \
            int r = id >> 5, q = id & 31;                                       \
            uint32_t col = (uint32_t)(q * 16) ^ ((r & 7) << 4);                 \
            cpasync16(_db + r * 512 + col,                                      \
                      T + (size_t)((kb) * 32 + r) * Hh + q * 8);                \
        }                                                                       \
        asm volatile("cp.async.commit_group;" ::: "memory");                    \
    }

    AISSUE(0);
    AISSUE(1);
    AISSUE(2);

    for (int kb = 0; kb < 16; kb++) {
        if (kb < 14)       asm volatile("cp.async.wait_group 2;" ::: "memory");
        else if (kb == 14) asm volatile("cp.async.wait_group 1;" ::: "memory");
        else               asm volatile("cp.async.wait_group 0;" ::: "memory");
        __syncthreads();

        uint32_t aA = smA + (kb % 3) * ACHB;
        uint32_t aB = smT + (kb % 3) * TCHB;

#pragma unroll
        for (int ks = 0; ks < 2; ks++) {
            const int k0 = ks * 16;
            uint32_t af[4][4], bf[8][2];
#pragma unroll
            for (int mi = 0; mi < 4; mi++) {
                uint32_t ad = aA + (mi * 16 + a_row) * (AST * 2) + (k0 + a_kc) * 2;
                ldsm_x4(af[mi][0], af[mi][1], af[mi][2], af[mi][3], ad);
            }
#pragma unroll
            for (int nip = 0; nip < 4; nip++) {
                int krow = k0 + bt_kr;
                int ncol = n_off + nip * 16 + bt_nc;
                uint32_t bd = aB + krow * 512 + (((uint32_t)(ncol * 2)) ^ ((krow & 7) << 4));
                ldsm_x4_t(bf[nip * 2][0], bf[nip * 2][1], bf[nip * 2 + 1][0], bf[nip * 2 + 1][1], bd);
            }
#pragma unroll
            for (int mi = 0; mi < 4; mi++)
#pragma unroll
                for (int ni = 0; ni < 8; ni++)
                    mma_bf16(acc[mi][ni], af[mi], bf[ni]);
        }
        __syncthreads();   // final iteration: all phase-1 smem reads complete after this
        if (kb + 3 < 16) AISSUE(kb + 3);
    }
#undef AISSUE

    // ---------- epilogue 1: bias + relu; pool; stage H to smem (aliases dead phase-1 bufs) ----------
    float pl0[8], pl1[8];
#pragma unroll
    for (int ni = 0; ni < 8; ni++) { pl0[ni] = 0.f; pl1[ni] = 0.f; }

#pragma unroll
    for (int mi = 0; mi < 4; mi++) {
#pragma unroll
        for (int ni = 0; ni < 8; ni++) {
            int c = n_off + ni * 8 + tig * 2;
            float b0 = bias[c], b1 = bias[c + 1];
            float v0 = fmaxf(acc[mi][ni][0] + b0, 0.f);
            float v1 = fmaxf(acc[mi][ni][1] + b1, 0.f);
            float v2 = fmaxf(acc[mi][ni][2] + b0, 0.f);
            float v3 = fmaxf(acc[mi][ni][3] + b1, 0.f);
            pl0[ni] += v0 + v2;
            pl1[ni] += v1 + v3;
            __nv_bfloat162 p0 = __float22bfloat162_rn(make_float2(v0, v1));
            __nv_bfloat162 p1 = __float22bfloat162_rn(make_float2(v2, v3));
            uint32_t h0 = smH + (mi * 16 + gid)     * HST + c * 2;
            uint32_t h1 = smH + (mi * 16 + gid + 8) * HST + c * 2;
            asm volatile("st.shared.b32 [%0], %1;" :: "r"(h0), "r"(*(uint32_t*)&p0) : "memory");
            asm volatile("st.shared.b32 [%0], %1;" :: "r"(h1), "r"(*(uint32_t*)&p1) : "memory");
        }
    }

    if (do_pool) {
#pragma unroll
        for (int ni = 0; ni < 8; ni++) {
            int c = n_off + ni * 8 + tig * 2;
            atomicAdd(&g_pool[task * Hh + c],     pl0[ni]);
            atomicAdd(&g_pool[task * Hh + c + 1], pl1[ni]);
        }
    }
    if (layer < 0) return;    // last layer: pool only

    __syncthreads();          // H stores visible; phase-1 buffers fully dead

    // ---------- phase 2: T' = H @ W  (8 k-chunks of 32, depth 2) ----------
    const __nv_bfloat16* W = g_Wtb + (size_t)layer * Hh * Hh;

#pragma unroll
    for (int mi = 0; mi < 4; mi++)
#pragma unroll
        for (int ni = 0; ni < 8; ni++)
#pragma unroll
            for (int q = 0; q < 4; q++) acc[mi][ni][q] = 0.f;

#define WISSUE(kc)                                                              \
    {                                                                           \
        uint32_t _dw = smW + ((kc) & 1) * WCH2;                                 \
        _Pragma("unroll")                                                       \
        for (int it = 0; it < 8; it++) {                                        \
            int id = tid + it * 128;                                            \
            int r = id >> 2, g = id & 3;                                        \
            cpasync16(_dw + r * (AST * 2) + g * 16,                             \
                      W + (size_t)r * Hh + (kc) * 32 + g * 8);                  \
        }                                                                       \
        asm volatile("cp.async.commit_group;" ::: "memory");                    \
    }

    WISSUE(0);
    WISSUE(1);

    for (int kc = 0; kc < 8; kc++) {
        if (kc == 7) asm volatile("cp.async.wait_group 0;" ::: "memory");
        else         asm volatile("cp.async.wait_group 1;" ::: "memory");
        __syncthreads();

        uint32_t aW = smW + (kc & 1) * WCH2;
#pragma unroll
        for (int ks = 0; ks < 2; ks++) {
            const int k0 = ks * 16;
            uint32_t af[4][4], bf[8][2];
#pragma unroll
            for (int mi = 0; mi < 4; mi++) {
                uint32_t ad = smH + (mi * 16 + a_row) * HST + (kc * 32 + k0 + a_kc) * 2;
                ldsm_x4(af[mi][0], af[mi][1], af[mi][2], af[mi][3], ad);
            }
#pragma unroll
            for (int nip = 0; nip < 4; nip++) {
                uint32_t bd = aW + (n_off + nip * 16 + b_row) * (AST * 2) + (k0 + b_kc) * 2;
                ldsm_x4(bf[nip * 2][0], bf[nip * 2][1], bf[nip * 2 + 1][0], bf[nip * 2 + 1][1], bd);
            }
#pragma unroll
            for (int mi = 0; mi < 4; mi++)
#pragma unroll
                for (int ni = 0; ni < 8; ni++)
                    mma_bf16(acc[mi][ni], af[mi], bf[ni]);
        }
        __syncthreads();
        if (kc + 2 < 8) WISSUE(kc + 2);
    }
#undef WISSUE

    // ---------- epilogue 2: pack T' pairs ----------
#pragma unroll
    for (int mi = 0; mi < 4; mi++) {
        int r0 = mi * 16 + gid;
#pragma unroll
        for (int ni = 0; ni < 8; ni++) {
            int pi = n_off / 2 + ni * 4 + tig;
            __nv_bfloat162 p0 = __float22bfloat162_rn(make_float2(acc[mi][ni][0], acc[mi][ni][1]));
            __nv_bfloat162 p1 = __float22bfloat162_rn(make_float2(acc[mi][ni][2], acc[mi][ni][3]));
            Co[(size_t)r0 * HP + pi]       = *reinterpret_cast<uint32_t*>(&p0);
            Co[(size_t)(r0 + 8) * HP + pi] = *reinterpret_cast<uint32_t*>(&p1);
        }
    }
}

// ---------------- FC head (pool scale folded in) ----------------
__global__ void fck(const float* __restrict__ hfeat, const float* __restrict__ afeat,
                    const float* __restrict__ fcW, const float* __restrict__ fcb,
                    float* __restrict__ out) {
    int g = blockIdx.x;
    int c = threadIdx.x >> 5;
    int lane = threadIdx.x & 31;
    const float ps = 1.0f / Nn;
    float acc = 0.f;
    for (int i = lane; i < 2 * (Hh + 6); i += 32) {
        float xv;
        if      (i < 256) xv = g_pool[g * Hh + i] * ps;
        else if (i < 262) xv = hfeat[g * 6 + (i - 256)];
        else if (i < 518) xv = g_pool[(Gn + g) * Hh + (i - 262)] * ps;
        else              xv = afeat[g * 6 + (i - 518)];
        acc += xv * fcW[i * 3 + c];
    }
#pragma unroll
    for (int o = 16; o; o >>= 1) acc += __shfl_down_sync(0xffffffff, acc, o);
    if (lane == 0) out[g * 3 + c] = acc + fcb[c];
}

// ---------------- launch ----------------
extern "C" void kernel_launch(void* const* d_in, const int* in_sizes, int n_in,
                              void* d_out, int out_size) {
    const float* home_x = (const float*)d_in[0];
    const float* away_x = (const float*)d_in[1];
    const int*   hei    = (const int*)d_in[2];
    const int*   aei    = (const int*)d_in[3];
    const float* hew    = (const float*)d_in[4];
    const float* aew    = (const float*)d_in[5];
    const float* hfeat  = (const float*)d_in[6];
    const float* afeat  = (const float*)d_in[7];
    const float* W0     = (const float*)d_in[8];
    const float* Wh     = (const float*)d_in[9];
    const float* bs     = (const float*)d_in[10];
    const float* fcW    = (const float*)d_in[11];
    const float* fcb    = (const float*)d_in[12];
    float* out = (float*)d_out;

    cudaFuncSetAttribute(layer_fused, cudaFuncAttributeMaxDynamicSharedMemorySize, FUS_SMEM);

    // prep: dinv/selfnorm, fused zero+build dense adjacency (L2-resident), bf16 weights
    prep_init<<<TASKS * Hh / 256, 256>>>();
    prep_degree<<<TASKS, 512>>>(hei, aei, hew, aew);
    build_Ad3<<<BAD_CTAS, 512>>>(hei, aei, hew, aew);
    wt_prep<<<dim3(Hh, 4), Hh>>>(Wh);

    // layer 0 input transform
    gemm0<<<dim3(TASKS, Nn / 8), 128>>>(home_x, away_x, W0);

    // 5 fused GCN layers: agg (+relu+bias) then feature GEMM of NEXT layer
    for (int l = 0; l < 5; l++) {
        layer_fused<<<dim3(8, TASKS), 128, FUS_SMEM>>>(
            l & 1,                 // T in/out ping-pong
            (l < 4) ? l : -1,      // weight index for phase 2; -1 = pool-only
            bs + l * Hh,
            (l == 4) ? 1 : 0);
    }

    // head
    fck<<<Gn, 96>>>(hfeat, afeat, fcW, fcb, out);
}